// round 4
// baseline (speedup 1.0000x reference)
#include <cuda_runtime.h>
#include <math.h>

#define BATCH 8192
#define SEQ 64
#define FEAT 65
#define KPAD 72
#define HID 128
#define G3 384
#define DZ 64

// ---------------- scratch (device globals; no allocation allowed) ----------
__device__ float    d_HtH[BATCH*64*64];          // 134 MB
__device__ float    d_Hty[BATCH*64];             // 2 MB
__device__ double   d_stats[128];
__device__ float    d_scale[64];
__device__ float    d_shift[64];
__device__ float    d_wsum[2*G3];
__device__ float    d_xg[402653184];             // (2*SEQ*BATCH*G3) 1.61 GB
__device__ float    d_h[2][2*BATCH*HID];         // ping-pong hidden (fp32)
__device__ float    d_go[134217728];             // (BATCH*SEQ*256) fp32
__device__ float    d_wx[BATCH*SEQ*DZ];          // 134 MB
__device__ float    d_gx[BATCH*256];
__device__ unsigned d_wih_hi[2*G3*KPAD];         // tf32 hi/lo weights
__device__ unsigned d_wih_lo[2*G3*KPAD];
__device__ unsigned d_whh_hi[2*G3*HID];
__device__ unsigned d_whh_lo[2*G3*HID];
__device__ unsigned d_wxw_hi[DZ*256];
__device__ unsigned d_wxw_lo[DZ*256];

// ---------------- tf32 helpers ---------------------------------------------
__device__ __forceinline__ unsigned f2tf(float x) {
    unsigned r; asm("cvt.rna.tf32.f32 %0, %1;" : "=r"(r) : "f"(x)); return r;
}
__device__ __forceinline__ void split_tf(float x, unsigned &hi, unsigned &lo) {
    hi = f2tf(x);
    lo = f2tf(x - __uint_as_float(hi));
}
__device__ __forceinline__ void mma_tf32(float c[4], unsigned a0, unsigned a1,
                                         unsigned a2, unsigned a3,
                                         unsigned b0, unsigned b1) {
    asm volatile(
        "mma.sync.aligned.m16n8k8.row.col.f32.tf32.tf32.f32 "
        "{%0,%1,%2,%3},{%4,%5,%6,%7},{%8,%9},{%0,%1,%2,%3};"
        : "+f"(c[0]), "+f"(c[1]), "+f"(c[2]), "+f"(c[3])
        : "r"(a0), "r"(a1), "r"(a2), "r"(a3), "r"(b0), "r"(b1));
}
// 3xTF32: C += (Ah+Al)*(Bh+Bl) dropping Al*Bl
__device__ __forceinline__ void mma3(float c[4],
                                     unsigned ah0, unsigned ah1, unsigned ah2, unsigned ah3,
                                     unsigned al0, unsigned al1, unsigned al2, unsigned al3,
                                     unsigned bh0, unsigned bh1,
                                     unsigned bl0, unsigned bl1) {
    mma_tf32(c, al0, al1, al2, al3, bh0, bh1);
    mma_tf32(c, ah0, ah1, ah2, ah3, bl0, bl1);
    mma_tf32(c, ah0, ah1, ah2, ah3, bh0, bh1);
}

// ---------------- init: zero stats + h0 ------------------------------------
__global__ __launch_bounds__(256) void k_init() {
    int idx = blockIdx.x*256 + threadIdx.x;
    if (idx < 2*BATCH*HID) d_h[0][idx] = 0.f;
    if (blockIdx.x == 0 && threadIdx.x < 128) d_stats[threadIdx.x] = 0.0;
}

// ---------------- weight prep: fp32 -> tf32 hi/lo ----------------------------
__global__ __launch_bounds__(256) void k_prep(const float* __restrict__ wih,
                                              const float* __restrict__ whh,
                                              const float* __restrict__ wx) {
    int idx = blockIdx.x*256 + threadIdx.x;
    if (idx < 2*G3*HID) {
        unsigned h, l; split_tf(whh[idx], h, l);
        d_whh_hi[idx] = h; d_whh_lo[idx] = l;
    }
    if (idx < 2*G3*KPAD) {
        int row = idx / KPAD, f = idx - row*KPAD;
        unsigned h = 0u, l = 0u;
        if (f < FEAT) split_tf(wih[row*FEAT + f], h, l);
        d_wih_hi[idx] = h; d_wih_lo[idx] = l;
    }
    if (idx < DZ*256) {
        unsigned h, l; split_tf(wx[idx], h, l);
        d_wxw_hi[idx] = h; d_wxw_lo[idx] = l;
    }
}

// ---------------- per-batch HtH, Hty + BN partial stats ---------------------
__global__ __launch_bounds__(256) void k_hth(const float* __restrict__ Hg,
                                             const float* __restrict__ yg) {
    int b = blockIdx.x;
    __shared__ float Hs[64][65];
    __shared__ float ys[64], hty[64], csum[64], csq[64];
    int tid = threadIdx.x;
    const float* Hb = Hg + (size_t)b*4096;
    for (int i = tid; i < 4096; i += 256) Hs[i>>6][i&63] = Hb[i];
    if (tid < 64) { ys[tid] = yg[b*64+tid]; csum[tid]=0.f; csq[tid]=0.f; }
    __syncthreads();
    if (tid < 64) {
        float a = 0.f;
#pragma unroll
        for (int r=0;r<64;r++) a += Hs[r][tid]*ys[r];
        hty[tid] = a;
        d_Hty[b*64+tid] = a;
    }
    int ty = tid >> 4, tx = tid & 15;
    float acc[4][4] = {};
#pragma unroll 8
    for (int r = 0; r < 64; r++) {
        float a[4], bb[4];
#pragma unroll
        for (int i=0;i<4;i++) a[i]  = Hs[r][ty*4+i];
#pragma unroll
        for (int j=0;j<4;j++) bb[j] = Hs[r][tx*4+j];
#pragma unroll
        for (int i=0;i<4;i++)
#pragma unroll
            for (int j=0;j<4;j++) acc[i][j] += a[i]*bb[j];
    }
    float* outp = d_HtH + (size_t)b*4096;
#pragma unroll
    for (int i=0;i<4;i++) {
        float4 v = make_float4(acc[i][0],acc[i][1],acc[i][2],acc[i][3]);
        *reinterpret_cast<float4*>(&outp[(ty*4+i)*64 + tx*4]) = v;
        float s1 = v.x+v.y+v.z+v.w;
        float s2 = v.x*v.x+v.y*v.y+v.z*v.z+v.w*v.w;
        atomicAdd(&csum[ty*4+i], s1);
        atomicAdd(&csq[ty*4+i],  s2);
    }
    __syncthreads();
    if (tid < 64) {
        float v = hty[tid];
        atomicAdd(&d_stats[tid],    (double)(csum[tid]+v));
        atomicAdd(&d_stats[64+tid], (double)(csq[tid]+v*v));
    }
}

// ---------------- finalize BN scale/shift + W_ih row sums -------------------
__global__ void k_bn(const float* __restrict__ gamma, const float* __restrict__ beta,
                     const float* __restrict__ wih) {
    int tid = threadIdx.x;
    if (tid < 64) {
        double n  = (double)BATCH*FEAT;
        double mu = d_stats[tid]/n;
        double var = d_stats[64+tid]/n - mu*mu;
        double sc = (double)gamma[tid] / sqrt(var + 1e-5);
        d_scale[tid] = (float)sc;
        d_shift[tid] = beta[tid] - (float)(mu*sc);
    }
    if (tid < 2*G3) {
        float s = 0.f;
        const float* w = wih + tid*FEAT;
        for (int f=0; f<FEAT; f++) s += w[f];
        d_wsum[tid] = s;
    }
}

// ---------------- GRU input gates via 3xTF32 mma ----------------------------
#define XG_SMEM (4*64*76*4)
__global__ __launch_bounds__(256) void k_xg(const float* __restrict__ bih) {
    extern __shared__ unsigned xsm[];
    unsigned (*Ah)[76] = (unsigned(*)[76])xsm;
    unsigned (*Al)[76] = (unsigned(*)[76])(xsm + 64*76);
    unsigned (*Bh)[76] = (unsigned(*)[76])(xsm + 2*64*76);
    unsigned (*Bl)[76] = (unsigned(*)[76])(xsm + 3*64*76);
    int z = blockIdx.z;            // dir*64 + s
    int dir = z >> 6, s = z & 63;
    int g0 = blockIdx.x*64, b0 = blockIdx.y*64;
    int tid = threadIdx.x;
    for (int i = tid; i < 64*KPAD; i += 256) {
        int m = i/KPAD, f = i - m*KPAD;
        float v = (f < 64) ? d_HtH[((size_t)(b0+m)*64 + s)*64 + f]
                 : (f == 64 ? d_Hty[(b0+m)*64 + s] : 0.f);
        unsigned h, l; split_tf(v, h, l);
        Ah[m][f] = h; Al[m][f] = l;
    }
    size_t wb = (size_t)dir*G3*KPAD;
    for (int i = tid; i < 64*KPAD; i += 256) {
        int g = i/KPAD, f = i - g*KPAD;
        Bh[g][f] = d_wih_hi[wb + (size_t)(g0+g)*KPAD + f];
        Bl[g][f] = d_wih_lo[wb + (size_t)(g0+g)*KPAD + f];
    }
    __syncthreads();
    int w = tid >> 5, lane = tid & 31, grp = lane >> 2, tg = lane & 3;
    int mrow = (w >> 1)*16, ncol = (w & 1)*32;
    float acc[4][4] = {};
#pragma unroll
    for (int kk = 0; kk < KPAD; kk += 8) {
        unsigned ah0 = Ah[mrow+grp][kk+tg],   ah1 = Ah[mrow+grp+8][kk+tg];
        unsigned ah2 = Ah[mrow+grp][kk+tg+4], ah3 = Ah[mrow+grp+8][kk+tg+4];
        unsigned al0 = Al[mrow+grp][kk+tg],   al1 = Al[mrow+grp+8][kk+tg];
        unsigned al2 = Al[mrow+grp][kk+tg+4], al3 = Al[mrow+grp+8][kk+tg+4];
#pragma unroll
        for (int nf = 0; nf < 4; nf++) {
            unsigned bh0 = Bh[ncol+nf*8+grp][kk+tg];
            unsigned bh1 = Bh[ncol+nf*8+grp][kk+tg+4];
            unsigned bl0 = Bl[ncol+nf*8+grp][kk+tg];
            unsigned bl1 = Bl[ncol+nf*8+grp][kk+tg+4];
            mma3(acc[nf], ah0,ah1,ah2,ah3, al0,al1,al2,al3, bh0,bh1, bl0,bl1);
        }
    }
    float sc = d_scale[s], sh = d_shift[s];
    size_t base = ((size_t)z*BATCH + b0)*G3;
#pragma unroll
    for (int nf = 0; nf < 4; nf++) {
        int c = g0 + ncol + nf*8 + tg*2;
        float w0 = sh*d_wsum[dir*G3+c]   + bih[dir*G3+c];
        float w1 = sh*d_wsum[dir*G3+c+1] + bih[dir*G3+c+1];
        float2 v0 = make_float2(acc[nf][0]*sc + w0, acc[nf][1]*sc + w1);
        float2 v1 = make_float2(acc[nf][2]*sc + w0, acc[nf][3]*sc + w1);
        *reinterpret_cast<float2*>(&d_xg[base + (size_t)(mrow+grp)*G3   + c]) = v0;
        *reinterpret_cast<float2*>(&d_xg[base + (size_t)(mrow+grp+8)*G3 + c]) = v1;
    }
}

// ---------------- fused GRU step: hg = h @ W_hh^T (3xTF32) + cell -----------
// smem: Ah[32][20] Al[32][20] Bh[384][20] Bl[384][20]; Gs[32][385] aliased.
#define GRU_A1   (32*20)            // u32 per A tile
#define GRU_B1   (384*20)
#define GRU_SMEM ((2*GRU_A1 + 2*GRU_B1)*4)

__global__ __launch_bounds__(256) void k_gru_step(const float* __restrict__ bhh,
                                                  int step, int ping) {
    extern __shared__ unsigned gsm[];
    unsigned (*Ah)[20] = (unsigned(*)[20])gsm;
    unsigned (*Al)[20] = (unsigned(*)[20])(gsm + GRU_A1);
    unsigned (*Bh)[20] = (unsigned(*)[20])(gsm + 2*GRU_A1);
    unsigned (*Bl)[20] = (unsigned(*)[20])(gsm + 2*GRU_A1 + GRU_B1);
    float    (*Gs)[385] = (float(*)[385])gsm;   // aliased after mma phase

    int dir = blockIdx.y;
    int b0  = blockIdx.x*32;
    int sx  = dir ? (63 - step) : step;
    int tid = threadIdx.x, w = tid >> 5, lane = tid & 31;
    int grp = lane >> 2, tg = lane & 3;
    int mrow = (w >> 2)*16, ncol = (w & 3)*96;

    const float* hp = d_h[ping] + (size_t)dir*BATCH*HID;
    size_t wb = (size_t)dir*G3*HID;
    float acc[12][4] = {};

    for (int kc = 0; kc < 8; kc++) {
        int k0 = kc*16;
        __syncthreads();
        for (int i = tid; i < 512; i += 256) {
            int m = i >> 4, k = i & 15;
            unsigned h, l; split_tf(hp[(size_t)(b0+m)*HID + k0 + k], h, l);
            Ah[m][k] = h; Al[m][k] = l;
        }
        for (int i = tid; i < 1536; i += 256) {
            int c = i >> 2, q = (i & 3)*4;
            uint4 vh = *reinterpret_cast<const uint4*>(&d_whh_hi[wb + (size_t)c*HID + k0 + q]);
            uint4 vl = *reinterpret_cast<const uint4*>(&d_whh_lo[wb + (size_t)c*HID + k0 + q]);
            *reinterpret_cast<uint4*>(&Bh[c][q]) = vh;
            *reinterpret_cast<uint4*>(&Bl[c][q]) = vl;
        }
        __syncthreads();
#pragma unroll
        for (int kk = 0; kk < 16; kk += 8) {
            unsigned ah0 = Ah[mrow+grp][kk+tg],   ah1 = Ah[mrow+grp+8][kk+tg];
            unsigned ah2 = Ah[mrow+grp][kk+tg+4], ah3 = Ah[mrow+grp+8][kk+tg+4];
            unsigned al0 = Al[mrow+grp][kk+tg],   al1 = Al[mrow+grp+8][kk+tg];
            unsigned al2 = Al[mrow+grp][kk+tg+4], al3 = Al[mrow+grp+8][kk+tg+4];
#pragma unroll
            for (int nf = 0; nf < 12; nf++) {
                unsigned bh0 = Bh[ncol+nf*8+grp][kk+tg];
                unsigned bh1 = Bh[ncol+nf*8+grp][kk+tg+4];
                unsigned bl0 = Bl[ncol+nf*8+grp][kk+tg];
                unsigned bl1 = Bl[ncol+nf*8+grp][kk+tg+4];
                mma3(acc[nf], ah0,ah1,ah2,ah3, al0,al1,al2,al3, bh0,bh1, bl0,bl1);
            }
        }
    }
    __syncthreads();     // all reads of A/B done; alias Gs over them
#pragma unroll
    for (int nf = 0; nf < 12; nf++) {
        int c = ncol + nf*8 + tg*2, r = mrow + grp;
        Gs[r][c]   = acc[nf][0]; Gs[r][c+1]   = acc[nf][1];
        Gs[r+8][c] = acc[nf][2]; Gs[r+8][c+1] = acc[nf][3];
    }
    __syncthreads();

    size_t xbase = ((size_t)(dir*64 + sx)*BATCH + b0)*G3;
    const float* bh = bhh + dir*G3;
    float* hout = d_h[1-ping] + (size_t)dir*BATCH*HID;
    for (int i = tid; i < 32*128; i += 256) {
        int b = i >> 7, j = i & 127;
        float xr = d_xg[xbase + (size_t)b*G3 + j];
        float xz = d_xg[xbase + (size_t)b*G3 + 128 + j];
        float xn = d_xg[xbase + (size_t)b*G3 + 256 + j];
        float hr = Gs[b][j]       + bh[j];
        float hz = Gs[b][128 + j] + bh[128 + j];
        float hn = Gs[b][256 + j] + bh[256 + j];
        float hprev = hp[(size_t)(b0+b)*HID + j];
        float r  = 1.f/(1.f + expf(-(xr+hr)));
        float zg = 1.f/(1.f + expf(-(xz+hz)));
        float n  = tanhf(xn + r*hn);
        float h  = (1.f - zg)*n + zg*hprev;
        hout[(size_t)(b0+b)*HID + j] = h;
        d_go[((size_t)(b0+b)*64 + sx)*256 + dir*128 + j] = h;
    }
}

// ---------------- w_x = go @ Wx^T (3xTF32) ----------------------------------
__global__ __launch_bounds__(256) void k_wx() {
    __shared__ unsigned Ah[64][36], Al[64][36], Bh[64][36], Bl[64][36];
    int m0 = blockIdx.x*64;
    int tid = threadIdx.x, w = tid >> 5, lane = tid & 31;
    int grp = lane >> 2, tg = lane & 3;
    int mrow = (w >> 1)*16, ncol = (w & 1)*32;
    float acc[4][4] = {};
    for (int kc = 0; kc < 8; kc++) {
        int k0 = kc*32;
        __syncthreads();
        for (int i = tid; i < 2048; i += 256) {
            int m = i >> 5, k = i & 31;
            unsigned h, l; split_tf(d_go[(size_t)(m0+m)*256 + k0 + k], h, l);
            Ah[m][k] = h; Al[m][k] = l;
        }
        for (int i = tid; i < 512; i += 256) {
            int m = i >> 3, q = (i & 7)*4;
            uint4 vh = *reinterpret_cast<const uint4*>(&d_wxw_hi[(size_t)m*256 + k0 + q]);
            uint4 vl = *reinterpret_cast<const uint4*>(&d_wxw_lo[(size_t)m*256 + k0 + q]);
            *reinterpret_cast<uint4*>(&Bh[m][q]) = vh;
            *reinterpret_cast<uint4*>(&Bl[m][q]) = vl;
        }
        __syncthreads();
#pragma unroll
        for (int kk = 0; kk < 32; kk += 8) {
            unsigned ah0 = Ah[mrow+grp][kk+tg],   ah1 = Ah[mrow+grp+8][kk+tg];
            unsigned ah2 = Ah[mrow+grp][kk+tg+4], ah3 = Ah[mrow+grp+8][kk+tg+4];
            unsigned al0 = Al[mrow+grp][kk+tg],   al1 = Al[mrow+grp+8][kk+tg];
            unsigned al2 = Al[mrow+grp][kk+tg+4], al3 = Al[mrow+grp+8][kk+tg+4];
#pragma unroll
            for (int nf = 0; nf < 4; nf++) {
                unsigned bh0 = Bh[ncol+nf*8+grp][kk+tg];
                unsigned bh1 = Bh[ncol+nf*8+grp][kk+tg+4];
                unsigned bl0 = Bl[ncol+nf*8+grp][kk+tg];
                unsigned bl1 = Bl[ncol+nf*8+grp][kk+tg+4];
                mma3(acc[nf], ah0,ah1,ah2,ah3, al0,al1,al2,al3, bh0,bh1, bl0,bl1);
            }
        }
    }
#pragma unroll
    for (int nf = 0; nf < 4; nf++) {
        int c = ncol + nf*8 + tg*2;
        *reinterpret_cast<float2*>(&d_wx[(size_t)(m0+mrow+grp)*64   + c]) =
            make_float2(acc[nf][0], acc[nf][1]);
        *reinterpret_cast<float2*>(&d_wx[(size_t)(m0+mrow+grp+8)*64 + c]) =
            make_float2(acc[nf][2], acc[nf][3]);
    }
}

// ---------------- gx[b,c] = sum_s go[b,s,c] * xhat[b,s] ---------------------
__global__ __launch_bounds__(256) void k_gx(const float* __restrict__ x_raw) {
    int b = blockIdx.x;
    int c = threadIdx.x;
    __shared__ float xh[64];
    if (c < 64) xh[c] = 2.f*x_raw[b*64+c] - 3.f;   // 2x - 2^RATE + 1, RATE=2
    __syncthreads();
    float acc = 0.f;
    const float* g = d_go + (size_t)b*64*256;
#pragma unroll 8
    for (int s=0;s<64;s++) acc += g[s*256+c]*xh[s];
    d_gx[(size_t)b*256 + c] = acc;
}

// ---------------- final per-batch: z0, GD loop, output ----------------------
__global__ __launch_bounds__(256) void k_final(const float* __restrict__ Wz,
                                               float* __restrict__ outp) {
    int b = blockIdx.x, tid = threadIdx.x;
    __shared__ float Ws[64][65];
    __shared__ float As[64][65];
    __shared__ float hy[64], zv[64], wh[64], t1[64], t2[64];
    __shared__ float gxs[256];
    for (int i=tid;i<4096;i+=256) Ws[i>>6][i&63] = d_wx[(size_t)b*4096 + i];
    for (int i=tid;i<4096;i+=256) As[i>>6][i&63] = d_HtH[(size_t)b*4096 + i];
    if (tid<64) hy[tid] = d_Hty[b*64+tid];
    gxs[tid] = d_gx[(size_t)b*256 + tid];
    __syncthreads();
    if (tid<64) {
        float a=0.f;
        const float* wz = Wz + tid*256;
#pragma unroll 8
        for (int c=0;c<256;c++) a += wz[c]*gxs[c];
        zv[tid] = a;
        float w=0.f;
#pragma unroll
        for (int s=0;s<64;s++) w += Ws[s][tid]*hy[s];
        wh[tid] = w;
    }
    __syncthreads();
    for (int it=0; it<10; it++) {
        if (tid<64) { float a=0.f;
#pragma unroll
            for (int zc=0;zc<64;zc++) a += Ws[tid][zc]*zv[zc];
            t1[tid]=a; }
        __syncthreads();
        if (tid<64) { float a=0.f;
#pragma unroll
            for (int u=0;u<64;u++) a += As[tid][u]*t1[u];
            t2[tid]=a; }
        __syncthreads();
        if (tid<64) { float a=0.f;
#pragma unroll
            for (int s=0;s<64;s++) a += Ws[s][tid]*t2[s];
            zv[tid] += 2e-6f*(wh[tid]-a); }
        __syncthreads();
    }
    if (tid<64) {
        float a=0.f;
#pragma unroll
        for (int zc=0;zc<64;zc++) a += Ws[tid][zc]*zv[zc];
        outp[b*64+tid] = a;
    }
}

// ---------------- launch ----------------------------------------------------
extern "C" void kernel_launch(void* const* d_in, const int* in_sizes, int n_in,
                              void* d_out, int out_size) {
    const float* y     = (const float*)d_in[0];
    const float* H     = (const float*)d_in[1];
    const float* xraw  = (const float*)d_in[2];
    const float* wih   = (const float*)d_in[3];
    const float* whh   = (const float*)d_in[4];
    const float* bih   = (const float*)d_in[5];
    const float* bhh   = (const float*)d_in[6];
    const float* Wz    = (const float*)d_in[7];
    const float* Wx    = (const float*)d_in[8];
    const float* gamma = (const float*)d_in[9];
    const float* beta  = (const float*)d_in[10];
    float* outp = (float*)d_out;

    cudaFuncSetAttribute(k_gru_step, cudaFuncAttributeMaxDynamicSharedMemorySize,
                         GRU_SMEM);
    cudaFuncSetAttribute(k_xg, cudaFuncAttributeMaxDynamicSharedMemorySize,
                         XG_SMEM);

    k_init<<<8192,256>>>();
    k_prep<<<384,256>>>(wih, whh, Wx);
    k_hth<<<BATCH,256>>>(H, y);
    k_bn<<<1,768>>>(gamma, beta, wih);
    dim3 gc(6,128,128);
    k_xg<<<gc,256,XG_SMEM>>>(bih);
    for (int step=0; step<64; step++) {
        dim3 gd(256,2);
        k_gru_step<<<gd,256,GRU_SMEM>>>(bhh, step, step & 1);
    }
    k_wx<<<8192,256>>>();
    k_gx<<<BATCH,256>>>(xraw);
    k_final<<<BATCH,256>>>(Wz, outp);
}

// round 5
// speedup vs baseline: 1.0121x; 1.0121x over previous
#include <cuda_runtime.h>
#include <math.h>

#define BATCH 8192
#define SEQ 64
#define FEAT 65
#define KPAD 72
#define HID 128
#define G3 384
#define DZ 64

// ---------------- scratch (device globals; no allocation allowed) ----------
__device__ float    d_HtH[BATCH*64*64];          // 134 MB
__device__ float    d_Hty[BATCH*64];             // 2 MB
__device__ double   d_stats[128];
__device__ float    d_scale[64];
__device__ float    d_shift[64];
__device__ float    d_wsum[2*G3];
__device__ float    d_xg[402653184];             // (2*SEQ*BATCH*G3) 1.61 GB
__device__ float    d_h[2][2*BATCH*HID];         // ping-pong hidden (fp32)
__device__ float    d_go[134217728];             // (BATCH*SEQ*256) fp32
__device__ float    d_wx[BATCH*SEQ*DZ];          // 134 MB
__device__ float    d_gx[BATCH*256];
__device__ unsigned d_wih_hi[2*G3*KPAD];         // tf32 hi/lo weights
__device__ unsigned d_wih_lo[2*G3*KPAD];
__device__ unsigned d_whh_hi[2*G3*HID];
__device__ unsigned d_whh_lo[2*G3*HID];
__device__ unsigned d_wxw_hi[DZ*256];
__device__ unsigned d_wxw_lo[DZ*256];

// ---------------- tf32 helpers ---------------------------------------------
__device__ __forceinline__ unsigned f2tf(float x) {
    unsigned r; asm("cvt.rna.tf32.f32 %0, %1;" : "=r"(r) : "f"(x)); return r;
}
__device__ __forceinline__ void split_tf(float x, unsigned &hi, unsigned &lo) {
    hi = f2tf(x);
    lo = f2tf(x - __uint_as_float(hi));
}
__device__ __forceinline__ void mma_tf32(float c[4], unsigned a0, unsigned a1,
                                         unsigned a2, unsigned a3,
                                         unsigned b0, unsigned b1) {
    asm volatile(
        "mma.sync.aligned.m16n8k8.row.col.f32.tf32.tf32.f32 "
        "{%0,%1,%2,%3},{%4,%5,%6,%7},{%8,%9},{%0,%1,%2,%3};"
        : "+f"(c[0]), "+f"(c[1]), "+f"(c[2]), "+f"(c[3])
        : "r"(a0), "r"(a1), "r"(a2), "r"(a3), "r"(b0), "r"(b1));
}
// 3xTF32: C += (Ah+Al)*(Bh+Bl) dropping Al*Bl
__device__ __forceinline__ void mma3(float c[4],
                                     unsigned ah0, unsigned ah1, unsigned ah2, unsigned ah3,
                                     unsigned al0, unsigned al1, unsigned al2, unsigned al3,
                                     unsigned bh0, unsigned bh1,
                                     unsigned bl0, unsigned bl1) {
    mma_tf32(c, al0, al1, al2, al3, bh0, bh1);
    mma_tf32(c, ah0, ah1, ah2, ah3, bl0, bl1);
    mma_tf32(c, ah0, ah1, ah2, ah3, bh0, bh1);
}

// ---------------- init: zero stats + h0 ------------------------------------
__global__ __launch_bounds__(256) void k_init() {
    int idx = blockIdx.x*256 + threadIdx.x;
    if (idx < 2*BATCH*HID) d_h[0][idx] = 0.f;
    if (blockIdx.x == 0 && threadIdx.x < 128) d_stats[threadIdx.x] = 0.0;
}

// ---------------- weight prep: fp32 -> tf32 hi/lo ----------------------------
__global__ __launch_bounds__(256) void k_prep(const float* __restrict__ wih,
                                              const float* __restrict__ whh,
                                              const float* __restrict__ wx) {
    int idx = blockIdx.x*256 + threadIdx.x;
    if (idx < 2*G3*HID) {
        unsigned h, l; split_tf(whh[idx], h, l);
        d_whh_hi[idx] = h; d_whh_lo[idx] = l;
    }
    if (idx < 2*G3*KPAD) {
        int row = idx / KPAD, f = idx - row*KPAD;
        unsigned h = 0u, l = 0u;
        if (f < FEAT) split_tf(wih[row*FEAT + f], h, l);
        d_wih_hi[idx] = h; d_wih_lo[idx] = l;
    }
    if (idx < DZ*256) {
        unsigned h, l; split_tf(wx[idx], h, l);
        d_wxw_hi[idx] = h; d_wxw_lo[idx] = l;
    }
}

// ---------------- per-batch HtH, Hty + BN partial stats ---------------------
__global__ __launch_bounds__(256) void k_hth(const float* __restrict__ Hg,
                                             const float* __restrict__ yg) {
    int b = blockIdx.x;
    __shared__ float Hs[64][65];
    __shared__ float ys[64], hty[64], csum[64], csq[64];
    int tid = threadIdx.x;
    const float* Hb = Hg + (size_t)b*4096;
    for (int i = tid; i < 4096; i += 256) Hs[i>>6][i&63] = Hb[i];
    if (tid < 64) { ys[tid] = yg[b*64+tid]; csum[tid]=0.f; csq[tid]=0.f; }
    __syncthreads();
    if (tid < 64) {
        float a = 0.f;
#pragma unroll
        for (int r=0;r<64;r++) a += Hs[r][tid]*ys[r];
        hty[tid] = a;
        d_Hty[b*64+tid] = a;
    }
    int ty = tid >> 4, tx = tid & 15;
    float acc[4][4] = {};
#pragma unroll 8
    for (int r = 0; r < 64; r++) {
        float a[4], bb[4];
#pragma unroll
        for (int i=0;i<4;i++) a[i]  = Hs[r][ty*4+i];
#pragma unroll
        for (int j=0;j<4;j++) bb[j] = Hs[r][tx*4+j];
#pragma unroll
        for (int i=0;i<4;i++)
#pragma unroll
            for (int j=0;j<4;j++) acc[i][j] += a[i]*bb[j];
    }
    float* outp = d_HtH + (size_t)b*4096;
#pragma unroll
    for (int i=0;i<4;i++) {
        float4 v = make_float4(acc[i][0],acc[i][1],acc[i][2],acc[i][3]);
        *reinterpret_cast<float4*>(&outp[(ty*4+i)*64 + tx*4]) = v;
        float s1 = v.x+v.y+v.z+v.w;
        float s2 = v.x*v.x+v.y*v.y+v.z*v.z+v.w*v.w;
        atomicAdd(&csum[ty*4+i], s1);
        atomicAdd(&csq[ty*4+i],  s2);
    }
    __syncthreads();
    if (tid < 64) {
        float v = hty[tid];
        atomicAdd(&d_stats[tid],    (double)(csum[tid]+v));
        atomicAdd(&d_stats[64+tid], (double)(csq[tid]+v*v));
    }
}

// ---------------- finalize BN scale/shift + W_ih row sums -------------------
__global__ void k_bn(const float* __restrict__ gamma, const float* __restrict__ beta,
                     const float* __restrict__ wih) {
    int tid = threadIdx.x;
    if (tid < 64) {
        double n  = (double)BATCH*FEAT;
        double mu = d_stats[tid]/n;
        double var = d_stats[64+tid]/n - mu*mu;
        double sc = (double)gamma[tid] / sqrt(var + 1e-5);
        d_scale[tid] = (float)sc;
        d_shift[tid] = beta[tid] - (float)(mu*sc);
    }
    if (tid < 2*G3) {
        float s = 0.f;
        const float* w = wih + tid*FEAT;
        for (int f=0; f<FEAT; f++) s += w[f];
        d_wsum[tid] = s;
    }
}

// ---------------- GRU input gates via 3xTF32 mma ----------------------------
#define XG_SMEM (4*64*76*4)
__global__ __launch_bounds__(256) void k_xg(const float* __restrict__ bih) {
    extern __shared__ unsigned xsm[];
    unsigned (*Ah)[76] = (unsigned(*)[76])xsm;
    unsigned (*Al)[76] = (unsigned(*)[76])(xsm + 64*76);
    unsigned (*Bh)[76] = (unsigned(*)[76])(xsm + 2*64*76);
    unsigned (*Bl)[76] = (unsigned(*)[76])(xsm + 3*64*76);
    int z = blockIdx.z;            // dir*64 + s
    int dir = z >> 6, s = z & 63;
    int g0 = blockIdx.x*64, b0 = blockIdx.y*64;
    int tid = threadIdx.x;
    for (int i = tid; i < 64*KPAD; i += 256) {
        int m = i/KPAD, f = i - m*KPAD;
        float v = (f < 64) ? d_HtH[((size_t)(b0+m)*64 + s)*64 + f]
                 : (f == 64 ? d_Hty[(b0+m)*64 + s] : 0.f);
        unsigned h, l; split_tf(v, h, l);
        Ah[m][f] = h; Al[m][f] = l;
    }
    size_t wb = (size_t)dir*G3*KPAD;
    for (int i = tid; i < 64*KPAD; i += 256) {
        int g = i/KPAD, f = i - g*KPAD;
        Bh[g][f] = d_wih_hi[wb + (size_t)(g0+g)*KPAD + f];
        Bl[g][f] = d_wih_lo[wb + (size_t)(g0+g)*KPAD + f];
    }
    __syncthreads();
    int w = tid >> 5, lane = tid & 31, grp = lane >> 2, tg = lane & 3;
    int mrow = (w >> 1)*16, ncol = (w & 1)*32;
    float acc[4][4] = {};
#pragma unroll
    for (int kk = 0; kk < KPAD; kk += 8) {
        unsigned ah0 = Ah[mrow+grp][kk+tg],   ah1 = Ah[mrow+grp+8][kk+tg];
        unsigned ah2 = Ah[mrow+grp][kk+tg+4], ah3 = Ah[mrow+grp+8][kk+tg+4];
        unsigned al0 = Al[mrow+grp][kk+tg],   al1 = Al[mrow+grp+8][kk+tg];
        unsigned al2 = Al[mrow+grp][kk+tg+4], al3 = Al[mrow+grp+8][kk+tg+4];
#pragma unroll
        for (int nf = 0; nf < 4; nf++) {
            unsigned bh0 = Bh[ncol+nf*8+grp][kk+tg];
            unsigned bh1 = Bh[ncol+nf*8+grp][kk+tg+4];
            unsigned bl0 = Bl[ncol+nf*8+grp][kk+tg];
            unsigned bl1 = Bl[ncol+nf*8+grp][kk+tg+4];
            mma3(acc[nf], ah0,ah1,ah2,ah3, al0,al1,al2,al3, bh0,bh1, bl0,bl1);
        }
    }
    float sc = d_scale[s], sh = d_shift[s];
    size_t base = ((size_t)z*BATCH + b0)*G3;
#pragma unroll
    for (int nf = 0; nf < 4; nf++) {
        int c = g0 + ncol + nf*8 + tg*2;
        float w0 = sh*d_wsum[dir*G3+c]   + bih[dir*G3+c];
        float w1 = sh*d_wsum[dir*G3+c+1] + bih[dir*G3+c+1];
        float2 v0 = make_float2(acc[nf][0]*sc + w0, acc[nf][1]*sc + w1);
        float2 v1 = make_float2(acc[nf][2]*sc + w0, acc[nf][3]*sc + w1);
        *reinterpret_cast<float2*>(&d_xg[base + (size_t)(mrow+grp)*G3   + c]) = v0;
        *reinterpret_cast<float2*>(&d_xg[base + (size_t)(mrow+grp+8)*G3 + c]) = v1;
    }
}

// ---------------- fused GRU step: hg = h @ W_hh^T (3xTF32) + cell -----------
// smem: Ah[32][20] Al[32][20] Bh[384][20] Bl[384][20]; Gs[32][385] aliased.
#define GRU_A1   (32*20)            // u32 per A tile
#define GRU_B1   (384*20)
#define GRU_SMEM ((2*GRU_A1 + 2*GRU_B1)*4)

__global__ __launch_bounds__(256) void k_gru_step(const float* __restrict__ bhh,
                                                  int step, int ping) {
    extern __shared__ unsigned gsm[];
    unsigned (*Ah)[20] = (unsigned(*)[20])gsm;
    unsigned (*Al)[20] = (unsigned(*)[20])(gsm + GRU_A1);
    unsigned (*Bh)[20] = (unsigned(*)[20])(gsm + 2*GRU_A1);
    unsigned (*Bl)[20] = (unsigned(*)[20])(gsm + 2*GRU_A1 + GRU_B1);
    float    (*Gs)[385] = (float(*)[385])gsm;   // aliased after mma phase

    int dir = blockIdx.y;
    int b0  = blockIdx.x*32;
    int sx  = dir ? (63 - step) : step;
    int tid = threadIdx.x, w = tid >> 5, lane = tid & 31;
    int grp = lane >> 2, tg = lane & 3;
    int mrow = (w >> 2)*16, ncol = (w & 3)*96;

    const float* hp = d_h[ping] + (size_t)dir*BATCH*HID;
    size_t wb = (size_t)dir*G3*HID;
    float acc[12][4] = {};

    for (int kc = 0; kc < 8; kc++) {
        int k0 = kc*16;
        __syncthreads();
        for (int i = tid; i < 512; i += 256) {
            int m = i >> 4, k = i & 15;
            unsigned h, l; split_tf(hp[(size_t)(b0+m)*HID + k0 + k], h, l);
            Ah[m][k] = h; Al[m][k] = l;
        }
        for (int i = tid; i < 1536; i += 256) {
            int c = i >> 2, q = (i & 3)*4;
            uint4 vh = *reinterpret_cast<const uint4*>(&d_whh_hi[wb + (size_t)c*HID + k0 + q]);
            uint4 vl = *reinterpret_cast<const uint4*>(&d_whh_lo[wb + (size_t)c*HID + k0 + q]);
            *reinterpret_cast<uint4*>(&Bh[c][q]) = vh;
            *reinterpret_cast<uint4*>(&Bl[c][q]) = vl;
        }
        __syncthreads();
#pragma unroll
        for (int kk = 0; kk < 16; kk += 8) {
            unsigned ah0 = Ah[mrow+grp][kk+tg],   ah1 = Ah[mrow+grp+8][kk+tg];
            unsigned ah2 = Ah[mrow+grp][kk+tg+4], ah3 = Ah[mrow+grp+8][kk+tg+4];
            unsigned al0 = Al[mrow+grp][kk+tg],   al1 = Al[mrow+grp+8][kk+tg];
            unsigned al2 = Al[mrow+grp][kk+tg+4], al3 = Al[mrow+grp+8][kk+tg+4];
#pragma unroll
            for (int nf = 0; nf < 12; nf++) {
                unsigned bh0 = Bh[ncol+nf*8+grp][kk+tg];
                unsigned bh1 = Bh[ncol+nf*8+grp][kk+tg+4];
                unsigned bl0 = Bl[ncol+nf*8+grp][kk+tg];
                unsigned bl1 = Bl[ncol+nf*8+grp][kk+tg+4];
                mma3(acc[nf], ah0,ah1,ah2,ah3, al0,al1,al2,al3, bh0,bh1, bl0,bl1);
            }
        }
    }
    __syncthreads();     // all reads of A/B done; alias Gs over them
#pragma unroll
    for (int nf = 0; nf < 12; nf++) {
        int c = ncol + nf*8 + tg*2, r = mrow + grp;
        Gs[r][c]   = acc[nf][0]; Gs[r][c+1]   = acc[nf][1];
        Gs[r+8][c] = acc[nf][2]; Gs[r+8][c+1] = acc[nf][3];
    }
    __syncthreads();

    size_t xbase = ((size_t)(dir*64 + sx)*BATCH + b0)*G3;
    const float* bh = bhh + dir*G3;
    float* hout = d_h[1-ping] + (size_t)dir*BATCH*HID;
    for (int i = tid; i < 32*128; i += 256) {
        int b = i >> 7, j = i & 127;
        float xr = d_xg[xbase + (size_t)b*G3 + j];
        float xz = d_xg[xbase + (size_t)b*G3 + 128 + j];
        float xn = d_xg[xbase + (size_t)b*G3 + 256 + j];
        float hr = Gs[b][j]       + bh[j];
        float hz = Gs[b][128 + j] + bh[128 + j];
        float hn = Gs[b][256 + j] + bh[256 + j];
        float hprev = hp[(size_t)(b0+b)*HID + j];
        float r  = 1.f/(1.f + expf(-(xr+hr)));
        float zg = 1.f/(1.f + expf(-(xz+hz)));
        float n  = tanhf(xn + r*hn);
        float h  = (1.f - zg)*n + zg*hprev;
        hout[(size_t)(b0+b)*HID + j] = h;
        d_go[((size_t)(b0+b)*64 + sx)*256 + dir*128 + j] = h;
    }
}

// ---------------- w_x = go @ Wx^T (3xTF32) ----------------------------------
__global__ __launch_bounds__(256) void k_wx() {
    __shared__ unsigned Ah[64][36], Al[64][36], Bh[64][36], Bl[64][36];
    int m0 = blockIdx.x*64;
    int tid = threadIdx.x, w = tid >> 5, lane = tid & 31;
    int grp = lane >> 2, tg = lane & 3;
    int mrow = (w >> 1)*16, ncol = (w & 1)*32;
    float acc[4][4] = {};
    for (int kc = 0; kc < 8; kc++) {
        int k0 = kc*32;
        __syncthreads();
        for (int i = tid; i < 2048; i += 256) {
            int m = i >> 5, k = i & 31;
            unsigned h, l; split_tf(d_go[(size_t)(m0+m)*256 + k0 + k], h, l);
            Ah[m][k] = h; Al[m][k] = l;
        }
        for (int i = tid; i < 512; i += 256) {
            int m = i >> 3, q = (i & 7)*4;
            uint4 vh = *reinterpret_cast<const uint4*>(&d_wxw_hi[(size_t)m*256 + k0 + q]);
            uint4 vl = *reinterpret_cast<const uint4*>(&d_wxw_lo[(size_t)m*256 + k0 + q]);
            *reinterpret_cast<uint4*>(&Bh[m][q]) = vh;
            *reinterpret_cast<uint4*>(&Bl[m][q]) = vl;
        }
        __syncthreads();
#pragma unroll
        for (int kk = 0; kk < 32; kk += 8) {
            unsigned ah0 = Ah[mrow+grp][kk+tg],   ah1 = Ah[mrow+grp+8][kk+tg];
            unsigned ah2 = Ah[mrow+grp][kk+tg+4], ah3 = Ah[mrow+grp+8][kk+tg+4];
            unsigned al0 = Al[mrow+grp][kk+tg],   al1 = Al[mrow+grp+8][kk+tg];
            unsigned al2 = Al[mrow+grp][kk+tg+4], al3 = Al[mrow+grp+8][kk+tg+4];
#pragma unroll
            for (int nf = 0; nf < 4; nf++) {
                unsigned bh0 = Bh[ncol+nf*8+grp][kk+tg];
                unsigned bh1 = Bh[ncol+nf*8+grp][kk+tg+4];
                unsigned bl0 = Bl[ncol+nf*8+grp][kk+tg];
                unsigned bl1 = Bl[ncol+nf*8+grp][kk+tg+4];
                mma3(acc[nf], ah0,ah1,ah2,ah3, al0,al1,al2,al3, bh0,bh1, bl0,bl1);
            }
        }
    }
#pragma unroll
    for (int nf = 0; nf < 4; nf++) {
        int c = ncol + nf*8 + tg*2;
        *reinterpret_cast<float2*>(&d_wx[(size_t)(m0+mrow+grp)*64   + c]) =
            make_float2(acc[nf][0], acc[nf][1]);
        *reinterpret_cast<float2*>(&d_wx[(size_t)(m0+mrow+grp+8)*64 + c]) =
            make_float2(acc[nf][2], acc[nf][3]);
    }
}

// ---------------- gx[b,c] = sum_s go[b,s,c] * xhat[b,s] ---------------------
__global__ __launch_bounds__(256) void k_gx(const float* __restrict__ x_raw) {
    int b = blockIdx.x;
    int c = threadIdx.x;
    __shared__ float xh[64];
    if (c < 64) xh[c] = 2.f*x_raw[b*64+c] - 3.f;   // 2x - 2^RATE + 1, RATE=2
    __syncthreads();
    float acc = 0.f;
    const float* g = d_go + (size_t)b*64*256;
#pragma unroll 8
    for (int s=0;s<64;s++) acc += g[s*256+c]*xh[s];
    d_gx[(size_t)b*256 + c] = acc;
}

// ---------------- final per-batch: z0, GD loop, output ----------------------
__global__ __launch_bounds__(256) void k_final(const float* __restrict__ Wz,
                                               float* __restrict__ outp) {
    int b = blockIdx.x, tid = threadIdx.x;
    __shared__ float Ws[64][65];
    __shared__ float As[64][65];
    __shared__ float hy[64], zv[64], wh[64], t1[64], t2[64];
    __shared__ float gxs[256];
    for (int i=tid;i<4096;i+=256) Ws[i>>6][i&63] = d_wx[(size_t)b*4096 + i];
    for (int i=tid;i<4096;i+=256) As[i>>6][i&63] = d_HtH[(size_t)b*4096 + i];
    if (tid<64) hy[tid] = d_Hty[b*64+tid];
    gxs[tid] = d_gx[(size_t)b*256 + tid];
    __syncthreads();
    if (tid<64) {
        float a=0.f;
        const float* wz = Wz + tid*256;
#pragma unroll 8
        for (int c=0;c<256;c++) a += wz[c]*gxs[c];
        zv[tid] = a;
        float w=0.f;
#pragma unroll
        for (int s=0;s<64;s++) w += Ws[s][tid]*hy[s];
        wh[tid] = w;
    }
    __syncthreads();
    for (int it=0; it<10; it++) {
        if (tid<64) { float a=0.f;
#pragma unroll
            for (int zc=0;zc<64;zc++) a += Ws[tid][zc]*zv[zc];
            t1[tid]=a; }
        __syncthreads();
        if (tid<64) { float a=0.f;
#pragma unroll
            for (int u=0;u<64;u++) a += As[tid][u]*t1[u];
            t2[tid]=a; }
        __syncthreads();
        if (tid<64) { float a=0.f;
#pragma unroll
            for (int s=0;s<64;s++) a += Ws[s][tid]*t2[s];
            zv[tid] += 2e-6f*(wh[tid]-a); }
        __syncthreads();
    }
    if (tid<64) {
        float a=0.f;
#pragma unroll
        for (int zc=0;zc<64;zc++) a += Ws[tid][zc]*zv[zc];
        outp[b*64+tid] = a;
    }
}

// ---------------- launch ----------------------------------------------------
extern "C" void kernel_launch(void* const* d_in, const int* in_sizes, int n_in,
                              void* d_out, int out_size) {
    const float* y     = (const float*)d_in[0];
    const float* H     = (const float*)d_in[1];
    const float* xraw  = (const float*)d_in[2];
    const float* wih   = (const float*)d_in[3];
    const float* whh   = (const float*)d_in[4];
    const float* bih   = (const float*)d_in[5];
    const float* bhh   = (const float*)d_in[6];
    const float* Wz    = (const float*)d_in[7];
    const float* Wx    = (const float*)d_in[8];
    const float* gamma = (const float*)d_in[9];
    const float* beta  = (const float*)d_in[10];
    float* outp = (float*)d_out;

    cudaFuncSetAttribute(k_gru_step, cudaFuncAttributeMaxDynamicSharedMemorySize,
                         GRU_SMEM);
    cudaFuncSetAttribute(k_xg, cudaFuncAttributeMaxDynamicSharedMemorySize,
                         XG_SMEM);

    k_init<<<8192,256>>>();
    k_prep<<<384,256>>>(wih, whh, Wx);
    k_hth<<<BATCH,256>>>(H, y);
    k_bn<<<1,768>>>(gamma, beta, wih);
    dim3 gc(6,128,128);
    k_xg<<<gc,256,XG_SMEM>>>(bih);
    for (int step=0; step<64; step++) {
        dim3 gd(256,2);
        k_gru_step<<<gd,256,GRU_SMEM>>>(bhh, step, step & 1);
    }
    k_wx<<<8192,256>>>();
    k_gx<<<BATCH,256>>>(xraw);
    k_final<<<BATCH,256>>>(Wz, outp);
}

// round 7
// speedup vs baseline: 1.6120x; 1.5928x over previous
#include <cuda_runtime.h>
#include <math.h>

#define BATCH 8192
#define SEQ 64
#define FEAT 65
#define KXG 68
#define HID 128
#define G3 384
#define DZ 64

typedef unsigned long long u64;

// ---------------- packed fp32x2 FMA (FFMA2) ---------------------------------
#define PK2(d, x)       asm("mov.b64 %0, {%1, %1};" : "=l"(d) : "f"(x))
#define FMA2(c, a, b)   asm("fma.rn.f32x2 %0, %1, %2, %0;" : "+l"(c) : "l"(a), "l"(b))
#define UPK2(lo, hi, s) asm("mov.b64 {%0, %1}, %2;" : "=f"(lo), "=f"(hi) : "l"(s))

// 8-row micro-step: one a value splat -> 4 FFMA2 against 4 b-pairs
#define ROW8(acc_i, av)  { u64 aa_; PK2(aa_, av); \
    FMA2(acc_i[0], aa_, b0.x); FMA2(acc_i[1], aa_, b0.y); \
    FMA2(acc_i[2], aa_, b1.x); FMA2(acc_i[3], aa_, b1.y); }

// ---------------- scratch (device globals; no allocation allowed) ----------
__device__ float  d_HtH[BATCH*64*64];            // 134 MB
__device__ float  d_Hty[BATCH*64];
__device__ double d_stats[128];
__device__ float  d_scale[64];
__device__ float  d_shift[64];
__device__ float  d_wsum[2*G3];
__device__ float  d_xg[402653184];               // (2*SEQ*BATCH*G3) 1.61 GB
__device__ float  d_h[2][2*BATCH*HID];
__device__ float  d_hg[2*BATCH*G3];
__device__ float  d_go[134217728];               // (BATCH*SEQ*256)
__device__ float  d_wx[BATCH*SEQ*DZ];
__device__ float  d_gx[BATCH*256];
__device__ float  d_wih_t[2*KXG*G3];             // W_ih transposed k-major, K pad 68
__device__ float  d_whh_t[2*HID*G3];             // W_hh transposed k-major
__device__ float  d_wxt[256*DZ];                 // Wx transposed k-major

// ---------------- init -------------------------------------------------------
__global__ __launch_bounds__(256) void k_init() {
    int idx = blockIdx.x*256 + threadIdx.x;
    if (idx < 2*BATCH*HID) d_h[0][idx] = 0.f;
    if (blockIdx.x == 0 && threadIdx.x < 128) d_stats[threadIdx.x] = 0.0;
}

// ---------------- weight prep: transpose to k-major --------------------------
__global__ __launch_bounds__(256) void k_prep(const float* __restrict__ wih,
                                              const float* __restrict__ whh,
                                              const float* __restrict__ wx) {
    int idx = blockIdx.x*256 + threadIdx.x;
    if (idx < 2*KXG*G3) {
        int g = idx % G3; int rest = idx / G3;
        int f = rest % KXG; int dir = rest / KXG;
        d_wih_t[idx] = (f < FEAT) ? wih[((size_t)dir*G3 + g)*FEAT + f] : 0.f;
    }
    if (idx < 2*HID*G3) {
        int g = idx % G3; int rest = idx / G3;
        int k = rest % HID; int dir = rest / HID;
        d_whh_t[idx] = whh[((size_t)dir*G3 + g)*HID + k];
    }
    if (idx < 256*DZ) {
        int n = idx & 63, k = idx >> 6;
        d_wxt[idx] = wx[n*256 + k];
    }
}

// ---------------- per-batch HtH, Hty + BN partial stats (f32x2) --------------
__global__ __launch_bounds__(256) void k_hth(const float* __restrict__ Hg,
                                             const float* __restrict__ yg) {
    int b = blockIdx.x;
    __shared__ float Hs[64][68];
    __shared__ float ys[64], hty[64], csum[64], csq[64];
    int tid = threadIdx.x;
    const float* Hb = Hg + (size_t)b*4096;
    for (int i = tid; i < 4096; i += 256) Hs[i>>6][i&63] = Hb[i];
    if (tid < 64) { ys[tid] = yg[b*64+tid]; csum[tid]=0.f; csq[tid]=0.f; }
    __syncthreads();
    if (tid < 64) {
        float a = 0.f;
#pragma unroll
        for (int r=0;r<64;r++) a += Hs[r][tid]*ys[r];
        hty[tid] = a;
        d_Hty[b*64+tid] = a;
    }
    int ty = tid >> 4, tx = tid & 15;
    u64 acc[4][2] = {};
#pragma unroll 8
    for (int r = 0; r < 64; r++) {
        float4 a = *(const float4*)&Hs[r][ty*4];
        ulonglong2 bb = *(const ulonglong2*)&Hs[r][tx*4];
        u64 aa;
        PK2(aa, a.x); FMA2(acc[0][0], aa, bb.x); FMA2(acc[0][1], aa, bb.y);
        PK2(aa, a.y); FMA2(acc[1][0], aa, bb.x); FMA2(acc[1][1], aa, bb.y);
        PK2(aa, a.z); FMA2(acc[2][0], aa, bb.x); FMA2(acc[2][1], aa, bb.y);
        PK2(aa, a.w); FMA2(acc[3][0], aa, bb.x); FMA2(acc[3][1], aa, bb.y);
    }
    float* outp = d_HtH + (size_t)b*4096;
#pragma unroll
    for (int i=0;i<4;i++) {
        float4 v;
        UPK2(v.x, v.y, acc[i][0]);
        UPK2(v.z, v.w, acc[i][1]);
        *reinterpret_cast<float4*>(&outp[(ty*4+i)*64 + tx*4]) = v;
        float s1 = v.x+v.y+v.z+v.w;
        float s2 = v.x*v.x+v.y*v.y+v.z*v.z+v.w*v.w;
        atomicAdd(&csum[ty*4+i], s1);
        atomicAdd(&csq[ty*4+i],  s2);
    }
    __syncthreads();
    if (tid < 64) {
        float v = hty[tid];
        atomicAdd(&d_stats[tid],    (double)(csum[tid]+v));
        atomicAdd(&d_stats[64+tid], (double)(csq[tid]+v*v));
    }
}

// ---------------- finalize BN scale/shift + W_ih row sums --------------------
__global__ void k_bn(const float* __restrict__ gamma, const float* __restrict__ beta,
                     const float* __restrict__ wih) {
    int tid = threadIdx.x;
    if (tid < 64) {
        double n  = (double)BATCH*FEAT;
        double mu = d_stats[tid]/n;
        double var = d_stats[64+tid]/n - mu*mu;
        double sc = (double)gamma[tid] / sqrt(var + 1e-5);
        d_scale[tid] = (float)sc;
        d_shift[tid] = beta[tid] - (float)(mu*sc);
    }
    if (tid < 2*G3) {
        float s = 0.f;
        const float* w = wih + tid*FEAT;
        for (int f=0; f<FEAT; f++) s += w[f];
        d_wsum[tid] = s;
    }
}

// ---------------- GRU input gates: 128x128 tile, f32x2 ------------------------
#define XG_SMEM (2*KXG*132*4)
__global__ __launch_bounds__(256,2) void k_xg(const float* __restrict__ bih) {
    extern __shared__ float xs[];
    float (*As)[132] = (float(*)[132])xs;             // [f][m]
    float (*Bs)[132] = (float(*)[132])(xs + KXG*132); // [f][n]
    int n0 = blockIdx.x*128, b0 = blockIdx.y*128;
    int z = blockIdx.z, dir = z >> 6, s = z & 63;
    int tid = threadIdx.x;
    // A fill: transpose HtH[:, s, :] slice (rows f-contiguous in global)
    for (int i = tid; i < 128*16; i += 256) {
        int m = i >> 4, f4 = (i & 15)*4;
        float4 v = *(const float4*)&d_HtH[(size_t)(b0+m)*4096 + s*64 + f4];
        As[f4+0][m]=v.x; As[f4+1][m]=v.y; As[f4+2][m]=v.z; As[f4+3][m]=v.w;
    }
    if (tid < 128) {
        As[64][tid] = d_Hty[(b0+tid)*64 + s];
        As[65][tid] = 0.f; As[66][tid] = 0.f; As[67][tid] = 0.f;
    }
    // B fill: pre-transposed W_ih, direct float4
    for (int i = tid; i < KXG*32; i += 256) {
        int f = i >> 5, n4 = (i & 31)*4;
        *(float4*)&Bs[f][n4] =
            *(const float4*)&d_wih_t[((size_t)dir*KXG + f)*G3 + n0 + n4];
    }
    __syncthreads();
    int ty = tid >> 4, tx = tid & 15;
    u64 acc[8][4] = {};
#pragma unroll 4
    for (int k = 0; k < KXG; k++) {
        float4 a0 = *(const float4*)&As[k][ty*8];
        float4 a1 = *(const float4*)&As[k][ty*8+4];
        ulonglong2 b0 = *(const ulonglong2*)&Bs[k][tx*8];
        ulonglong2 b1 = *(const ulonglong2*)&Bs[k][tx*8+4];
        ROW8(acc[0], a0.x) ROW8(acc[1], a0.y) ROW8(acc[2], a0.z) ROW8(acc[3], a0.w)
        ROW8(acc[4], a1.x) ROW8(acc[5], a1.y) ROW8(acc[6], a1.z) ROW8(acc[7], a1.w)
    }
    float sc = d_scale[s], sh = d_shift[s];
    int gn = n0 + tx*8;
    float wv[8];
#pragma unroll
    for (int j=0;j<8;j++) wv[j] = sh*d_wsum[dir*G3+gn+j] + bih[dir*G3+gn+j];
    size_t zb = ((size_t)z*BATCH + b0)*G3;
#pragma unroll
    for (int i=0;i<8;i++) {
        int m = ty*8 + i;
        float o[8];
#pragma unroll
        for (int j=0;j<4;j++) {
            float lo, hi; UPK2(lo, hi, acc[i][j]);
            o[2*j]   = lo*sc + wv[2*j];
            o[2*j+1] = hi*sc + wv[2*j+1];
        }
        *(float4*)&d_xg[zb + (size_t)m*G3 + gn]     = make_float4(o[0],o[1],o[2],o[3]);
        *(float4*)&d_xg[zb + (size_t)m*G3 + gn + 4] = make_float4(o[4],o[5],o[6],o[7]);
    }
}

// ---------------- GRU hidden GEMM: hg = h @ W_hh^T, 128x128 tile, f32x2 ------
__global__ __launch_bounds__(256,2) void k_gru_gemm(int ping) {
    __shared__ float As[32][132];   // [k][m]
    __shared__ float Bs[32][132];   // [k][n]
    int n0 = blockIdx.x*128, b0 = blockIdx.y*128, dir = blockIdx.z;
    int tid = threadIdx.x, ty = tid >> 4, tx = tid & 15;
    const float* hp = d_h[ping] + (size_t)dir*BATCH*HID;
    const float* wt = d_whh_t + (size_t)dir*HID*G3;
    u64 acc[8][4] = {};
    for (int kc = 0; kc < 4; kc++) {
        __syncthreads();
#pragma unroll
        for (int p = 0; p < 4; p++) {
            int i = p*256 + tid;
            int m = i >> 3, k4 = (i & 7)*4;
            float4 v = *(const float4*)&hp[(size_t)(b0+m)*HID + kc*32 + k4];
            As[k4+0][m]=v.x; As[k4+1][m]=v.y; As[k4+2][m]=v.z; As[k4+3][m]=v.w;
        }
        for (int i = tid; i < 32*32; i += 256) {
            int k = i >> 5, n4 = (i & 31)*4;
            *(float4*)&Bs[k][n4] =
                *(const float4*)&wt[(size_t)(kc*32+k)*G3 + n0 + n4];
        }
        __syncthreads();
#pragma unroll 4
        for (int k = 0; k < 32; k++) {
            float4 a0 = *(const float4*)&As[k][ty*8];
            float4 a1 = *(const float4*)&As[k][ty*8+4];
            ulonglong2 b0 = *(const ulonglong2*)&Bs[k][tx*8];
            ulonglong2 b1 = *(const ulonglong2*)&Bs[k][tx*8+4];
            ROW8(acc[0], a0.x) ROW8(acc[1], a0.y) ROW8(acc[2], a0.z) ROW8(acc[3], a0.w)
            ROW8(acc[4], a1.x) ROW8(acc[5], a1.y) ROW8(acc[6], a1.z) ROW8(acc[7], a1.w)
        }
    }
    float* outp = d_hg + (size_t)dir*BATCH*G3;
#pragma unroll
    for (int i=0;i<8;i++) {
        int m = b0 + ty*8 + i;
        float o[8];
#pragma unroll
        for (int j=0;j<4;j++) UPK2(o[2*j], o[2*j+1], acc[i][j]);
        *(float4*)&outp[(size_t)m*G3 + n0 + tx*8]     = make_float4(o[0],o[1],o[2],o[3]);
        *(float4*)&outp[(size_t)m*G3 + n0 + tx*8 + 4] = make_float4(o[4],o[5],o[6],o[7]);
    }
}

// ---------------- GRU pointwise cell ------------------------------------------
__global__ __launch_bounds__(256) void k_gru_cell(const float* __restrict__ bhh,
                                                  int step, int ping) {
    int b = blockIdx.x;
    int tid = threadIdx.x;
    int dir = tid >> 7, j = tid & 127;
    int sx = dir ? (63 - step) : step;
    size_t xb = ((size_t)(dir*64 + sx)*BATCH + b)*G3;
    const float* hgb = d_hg + (size_t)dir*BATCH*G3 + (size_t)b*G3;
    const float* bh  = bhh + dir*G3;
    float xr = d_xg[xb + j], xz = d_xg[xb + 128 + j], xn = d_xg[xb + 256 + j];
    float hr = hgb[j]       + bh[j];
    float hz = hgb[128 + j] + bh[128 + j];
    float hn = hgb[256 + j] + bh[256 + j];
    float hprev = d_h[ping][(size_t)dir*BATCH*HID + b*HID + j];
    float r  = 1.f/(1.f + expf(-(xr+hr)));
    float zg = 1.f/(1.f + expf(-(xz+hz)));
    float n  = tanhf(xn + r*hn);
    float h  = (1.f - zg)*n + zg*hprev;
    d_h[1-ping][(size_t)dir*BATCH*HID + b*HID + j] = h;
    d_go[((size_t)b*64 + sx)*256 + dir*128 + j] = h;
}

// ---------------- w_x = go @ Wx^T: 256x64 tile, f32x2 -------------------------
__global__ __launch_bounds__(256,2) void k_wx() {
    __shared__ float As[32][260];   // [k][m], 256 m
    __shared__ float Bs[32][68];    // [k][n], 64 n
    int m0 = blockIdx.x*256;
    int tid = threadIdx.x, ty = tid >> 3, tx = tid & 7;
    u64 acc[8][4] = {};
    for (int kc = 0; kc < 8; kc++) {
        __syncthreads();
#pragma unroll
        for (int p = 0; p < 8; p++) {
            int i = p*256 + tid;
            int m = i >> 3, k4 = (i & 7)*4;
            float4 v = *(const float4*)&d_go[(size_t)(m0+m)*256 + kc*32 + k4];
            As[k4+0][m]=v.x; As[k4+1][m]=v.y; As[k4+2][m]=v.z; As[k4+3][m]=v.w;
        }
        for (int i = tid; i < 32*16; i += 256) {
            int k = i >> 4, n4 = (i & 15)*4;
            *(float4*)&Bs[k][n4] = *(const float4*)&d_wxt[(size_t)(kc*32+k)*64 + n4];
        }
        __syncthreads();
#pragma unroll 4
        for (int k = 0; k < 32; k++) {
            float4 a0 = *(const float4*)&As[k][ty*8];
            float4 a1 = *(const float4*)&As[k][ty*8+4];
            ulonglong2 b0 = *(const ulonglong2*)&Bs[k][tx*8];
            ulonglong2 b1 = *(const ulonglong2*)&Bs[k][tx*8+4];
            ROW8(acc[0], a0.x) ROW8(acc[1], a0.y) ROW8(acc[2], a0.z) ROW8(acc[3], a0.w)
            ROW8(acc[4], a1.x) ROW8(acc[5], a1.y) ROW8(acc[6], a1.z) ROW8(acc[7], a1.w)
        }
    }
#pragma unroll
    for (int i=0;i<8;i++) {
        int m = m0 + ty*8 + i;
        float o[8];
#pragma unroll
        for (int j=0;j<4;j++) UPK2(o[2*j], o[2*j+1], acc[i][j]);
        *(float4*)&d_wx[(size_t)m*64 + tx*8]     = make_float4(o[0],o[1],o[2],o[3]);
        *(float4*)&d_wx[(size_t)m*64 + tx*8 + 4] = make_float4(o[4],o[5],o[6],o[7]);
    }
}

// ---------------- gx[b,c] = sum_s go[b,s,c] * xhat[b,s] -----------------------
__global__ __launch_bounds__(256) void k_gx(const float* __restrict__ x_raw) {
    int b = blockIdx.x;
    int c = threadIdx.x;
    __shared__ float xh[64];
    if (c < 64) xh[c] = 2.f*x_raw[b*64+c] - 3.f;
    __syncthreads();
    float acc = 0.f;
    const float* g = d_go + (size_t)b*64*256;
#pragma unroll 8
    for (int s=0;s<64;s++) acc += g[s*256+c]*xh[s];
    d_gx[(size_t)b*256 + c] = acc;
}

// ---------------- final per-batch: z0, GD loop, output ------------------------
__global__ __launch_bounds__(256) void k_final(const float* __restrict__ Wz,
                                               float* __restrict__ outp) {
    int b = blockIdx.x, tid = threadIdx.x;
    __shared__ float Ws[64][65];
    __shared__ float As[64][65];
    __shared__ float hy[64], zv[64], wh[64], t1[64], t2[64];
    __shared__ float gxs[256];
    for (int i=tid;i<4096;i+=256) Ws[i>>6][i&63] = d_wx[(size_t)b*4096 + i];
    for (int i=tid;i<4096;i+=256) As[i>>6][i&63] = d_HtH[(size_t)b*4096 + i];
    if (tid<64) hy[tid] = d_Hty[b*64+tid];
    gxs[tid] = d_gx[(size_t)b*256 + tid];
    __syncthreads();
    if (tid<64) {
        float a=0.f;
        const float* wz = Wz + tid*256;
#pragma unroll 8
        for (int c=0;c<256;c++) a += wz[c]*gxs[c];
        zv[tid] = a;
        float w=0.f;
#pragma unroll
        for (int s=0;s<64;s++) w += Ws[s][tid]*hy[s];
        wh[tid] = w;
    }
    __syncthreads();
    for (int it=0; it<10; it++) {
        if (tid<64) { float a=0.f;
#pragma unroll
            for (int zc=0;zc<64;zc++) a += Ws[tid][zc]*zv[zc];
            t1[tid]=a; }
        __syncthreads();
        if (tid<64) { float a=0.f;
#pragma unroll
            for (int u=0;u<64;u++) a += As[tid][u]*t1[u];
            t2[tid]=a; }
        __syncthreads();
        if (tid<64) { float a=0.f;
#pragma unroll
            for (int s=0;s<64;s++) a += Ws[s][tid]*t2[s];
            zv[tid] += 2e-6f*(wh[tid]-a); }
        __syncthreads();
    }
    if (tid<64) {
        float a=0.f;
#pragma unroll
        for (int zc=0;zc<64;zc++) a += Ws[tid][zc]*zv[zc];
        outp[b*64+tid] = a;
    }
}

// ---------------- launch -------------------------------------------------------
extern "C" void kernel_launch(void* const* d_in, const int* in_sizes, int n_in,
                              void* d_out, int out_size) {
    const float* y     = (const float*)d_in[0];
    const float* H     = (const float*)d_in[1];
    const float* xraw  = (const float*)d_in[2];
    const float* wih   = (const float*)d_in[3];
    const float* whh   = (const float*)d_in[4];
    const float* bih   = (const float*)d_in[5];
    const float* bhh   = (const float*)d_in[6];
    const float* Wz    = (const float*)d_in[7];
    const float* Wx    = (const float*)d_in[8];
    const float* gamma = (const float*)d_in[9];
    const float* beta  = (const float*)d_in[10];
    float* outp = (float*)d_out;

    cudaFuncSetAttribute(k_xg, cudaFuncAttributeMaxDynamicSharedMemorySize, XG_SMEM);

    k_init<<<8192,256>>>();
    k_prep<<<384,256>>>(wih, whh, Wx);
    k_hth<<<BATCH,256>>>(H, y);
    k_bn<<<1,768>>>(gamma, beta, wih);
    k_xg<<<dim3(3,64,128),256,XG_SMEM>>>(bih);
    for (int step=0; step<64; step++) {
        k_gru_gemm<<<dim3(3,64,2),256>>>(step & 1);
        k_gru_cell<<<BATCH,256>>>(bhh, step, step & 1);
    }
    k_wx<<<2048,256>>>();
    k_gx<<<BATCH,256>>>(xraw);
    k_final<<<BATCH,256>>>(Wz, outp);
}

// round 9
// speedup vs baseline: 1.7288x; 1.0725x over previous
#include <cuda_runtime.h>
#include <math.h>

#define BATCH 8192
#define SEQ 64
#define FEAT 65
#define KXG 68
#define HID 128
#define G3 384
#define DZ 64

typedef unsigned long long u64;

// ---------------- packed fp32x2 FMA (FFMA2) ---------------------------------
#define PK2(d, x)       asm("mov.b64 %0, {%1, %1};" : "=l"(d) : "f"(x))
#define FMA2(c, a, b)   asm("fma.rn.f32x2 %0, %1, %2, %0;" : "+l"(c) : "l"(a), "l"(b))
#define UPK2(lo, hi, s) asm("mov.b64 {%0, %1}, %2;" : "=f"(lo), "=f"(hi) : "l"(s))

#define ROW8(acc_i, av)  { u64 aa_; PK2(aa_, av); \
    FMA2(acc_i[0], aa_, b0.x); FMA2(acc_i[1], aa_, b0.y); \
    FMA2(acc_i[2], aa_, b1.x); FMA2(acc_i[3], aa_, b1.y); }

// ---------------- scratch (device globals; no allocation allowed) ----------
__device__ float  d_HtH[BATCH*64*64];
__device__ float  d_Hty[BATCH*64];
__device__ double d_stats[128];
__device__ float  d_scale[64];
__device__ float  d_shift[64];
__device__ float  d_wsum[2*G3];
__device__ float  d_xg[402653184];               // (2*SEQ*BATCH*G3)
__device__ float  d_h[2][2*BATCH*HID];
__device__ float  d_go[134217728];               // (BATCH*SEQ*256)
__device__ float  d_wx[BATCH*SEQ*DZ];
__device__ float  d_gx[BATCH*256];
__device__ float  d_wih_t[2*KXG*G3];
__device__ float  d_whh_t[2*HID*G3];
__device__ float  d_wxt[256*DZ];

// ---------------- init -------------------------------------------------------
__global__ __launch_bounds__(256) void k_init() {
    int idx = blockIdx.x*256 + threadIdx.x;
    if (idx < 2*BATCH*HID) d_h[0][idx] = 0.f;
    if (blockIdx.x == 0 && threadIdx.x < 128) d_stats[threadIdx.x] = 0.0;
}

// ---------------- weight prep: transpose to k-major --------------------------
__global__ __launch_bounds__(256) void k_prep(const float* __restrict__ wih,
                                              const float* __restrict__ whh,
                                              const float* __restrict__ wx) {
    int idx = blockIdx.x*256 + threadIdx.x;
    if (idx < 2*KXG*G3) {
        int g = idx % G3; int rest = idx / G3;
        int f = rest % KXG; int dir = rest / KXG;
        d_wih_t[idx] = (f < FEAT) ? wih[((size_t)dir*G3 + g)*FEAT + f] : 0.f;
    }
    if (idx < 2*HID*G3) {
        int g = idx % G3; int rest = idx / G3;
        int k = rest % HID; int dir = rest / HID;
        d_whh_t[idx] = whh[((size_t)dir*G3 + g)*HID + k];
    }
    if (idx < 256*DZ) {
        int n = idx & 63, k = idx >> 6;
        d_wxt[idx] = wx[n*256 + k];
    }
}

// ---------------- per-batch HtH, Hty + BN partial stats (f32x2) --------------
__global__ __launch_bounds__(256) void k_hth(const float* __restrict__ Hg,
                                             const float* __restrict__ yg) {
    int b = blockIdx.x;
    __shared__ __align__(16) float Hs[64][68];
    __shared__ float ys[64], hty[64], csum[64], csq[64];
    int tid = threadIdx.x;
    const float* Hb = Hg + (size_t)b*4096;
    for (int i = tid; i < 4096; i += 256) Hs[i>>6][i&63] = Hb[i];
    if (tid < 64) { ys[tid] = yg[b*64+tid]; csum[tid]=0.f; csq[tid]=0.f; }
    __syncthreads();
    if (tid < 64) {
        float a = 0.f;
#pragma unroll
        for (int r=0;r<64;r++) a += Hs[r][tid]*ys[r];
        hty[tid] = a;
        d_Hty[b*64+tid] = a;
    }
    int ty = tid >> 4, tx = tid & 15;
    u64 acc[4][2] = {};
#pragma unroll 8
    for (int r = 0; r < 64; r++) {
        float4 a = *(const float4*)&Hs[r][ty*4];
        ulonglong2 bb = *(const ulonglong2*)&Hs[r][tx*4];
        u64 aa;
        PK2(aa, a.x); FMA2(acc[0][0], aa, bb.x); FMA2(acc[0][1], aa, bb.y);
        PK2(aa, a.y); FMA2(acc[1][0], aa, bb.x); FMA2(acc[1][1], aa, bb.y);
        PK2(aa, a.z); FMA2(acc[2][0], aa, bb.x); FMA2(acc[2][1], aa, bb.y);
        PK2(aa, a.w); FMA2(acc[3][0], aa, bb.x); FMA2(acc[3][1], aa, bb.y);
    }
    float* outp = d_HtH + (size_t)b*4096;
#pragma unroll
    for (int i=0;i<4;i++) {
        float4 v;
        UPK2(v.x, v.y, acc[i][0]);
        UPK2(v.z, v.w, acc[i][1]);
        *reinterpret_cast<float4*>(&outp[(ty*4+i)*64 + tx*4]) = v;
        float s1 = v.x+v.y+v.z+v.w;
        float s2 = v.x*v.x+v.y*v.y+v.z*v.z+v.w*v.w;
        atomicAdd(&csum[ty*4+i], s1);
        atomicAdd(&csq[ty*4+i],  s2);
    }
    __syncthreads();
    if (tid < 64) {
        float v = hty[tid];
        atomicAdd(&d_stats[tid],    (double)(csum[tid]+v));
        atomicAdd(&d_stats[64+tid], (double)(csq[tid]+v*v));
    }
}

// ---------------- finalize BN scale/shift + W_ih row sums --------------------
__global__ void k_bn(const float* __restrict__ gamma, const float* __restrict__ beta,
                     const float* __restrict__ wih) {
    int tid = threadIdx.x;
    if (tid < 64) {
        double n  = (double)BATCH*FEAT;
        double mu = d_stats[tid]/n;
        double var = d_stats[64+tid]/n - mu*mu;
        double sc = (double)gamma[tid] / sqrt(var + 1e-5);
        d_scale[tid] = (float)sc;
        d_shift[tid] = beta[tid] - (float)(mu*sc);
    }
    if (tid < 2*G3) {
        float s = 0.f;
        const float* w = wih + tid*FEAT;
        for (int f=0; f<FEAT; f++) s += w[f];
        d_wsum[tid] = s;
    }
}

// ---------------- GRU input gates: 128x128 tile, f32x2 ------------------------
#define XG_SMEM (2*KXG*132*4)
__global__ __launch_bounds__(256,2) void k_xg(const float* __restrict__ bih) {
    extern __shared__ __align__(16) float xs[];
    float (*As)[132] = (float(*)[132])xs;
    float (*Bs)[132] = (float(*)[132])(xs + KXG*132);
    int n0 = blockIdx.x*128, b0 = blockIdx.y*128;
    int z = blockIdx.z, dir = z >> 6, s = z & 63;
    int tid = threadIdx.x;
    for (int i = tid; i < 128*16; i += 256) {
        int m = i >> 4, f4 = (i & 15)*4;
        float4 v = *(const float4*)&d_HtH[(size_t)(b0+m)*4096 + s*64 + f4];
        As[f4+0][m]=v.x; As[f4+1][m]=v.y; As[f4+2][m]=v.z; As[f4+3][m]=v.w;
    }
    if (tid < 128) {
        As[64][tid] = d_Hty[(b0+tid)*64 + s];
        As[65][tid] = 0.f; As[66][tid] = 0.f; As[67][tid] = 0.f;
    }
    for (int i = tid; i < KXG*32; i += 256) {
        int f = i >> 5, n4 = (i & 31)*4;
        *(float4*)&Bs[f][n4] =
            *(const float4*)&d_wih_t[((size_t)dir*KXG + f)*G3 + n0 + n4];
    }
    __syncthreads();
    int ty = tid >> 4, tx = tid & 15;
    u64 acc[8][4] = {};
#pragma unroll 4
    for (int k = 0; k < KXG; k++) {
        float4 a0 = *(const float4*)&As[k][ty*8];
        float4 a1 = *(const float4*)&As[k][ty*8+4];
        ulonglong2 b0 = *(const ulonglong2*)&Bs[k][tx*8];
        ulonglong2 b1 = *(const ulonglong2*)&Bs[k][tx*8+4];
        ROW8(acc[0], a0.x) ROW8(acc[1], a0.y) ROW8(acc[2], a0.z) ROW8(acc[3], a0.w)
        ROW8(acc[4], a1.x) ROW8(acc[5], a1.y) ROW8(acc[6], a1.z) ROW8(acc[7], a1.w)
    }
    float sc = d_scale[s], sh = d_shift[s];
    int gn = n0 + tx*8;
    float wv[8];
#pragma unroll
    for (int j=0;j<8;j++) wv[j] = sh*d_wsum[dir*G3+gn+j] + bih[dir*G3+gn+j];
    size_t zb = ((size_t)z*BATCH + b0)*G3;
#pragma unroll
    for (int i=0;i<8;i++) {
        int m = ty*8 + i;
        float o[8];
#pragma unroll
        for (int j=0;j<4;j++) {
            float lo, hi; UPK2(lo, hi, acc[i][j]);
            o[2*j]   = lo*sc + wv[2*j];
            o[2*j+1] = hi*sc + wv[2*j+1];
        }
        *(float4*)&d_xg[zb + (size_t)m*G3 + gn]     = make_float4(o[0],o[1],o[2],o[3]);
        *(float4*)&d_xg[zb + (size_t)m*G3 + gn + 4] = make_float4(o[4],o[5],o[6],o[7]);
    }
}

// ---------------- FUSED GRU step: gemm (f32x2) + cell in registers ------------
// grid (256, 2): 32-batch tile, dir. 256 threads = 4(m) x 64(n).
// thread outputs: rows ty*8..+7, cols {j0,j0+1} of each gate (j0 = tx*2).
__global__ __launch_bounds__(256,2) void k_gru_step(const float* __restrict__ bhh,
                                                    int step, int ping) {
    __shared__ __align__(16) float As[32][36];    // [k][m], 144B rows (16-aligned)
    __shared__ __align__(16) float Bs[32][388];   // [k][gate-col], 1552B rows (8-aligned)
    int dir = blockIdx.y, b0 = blockIdx.x*32;
    int sx = dir ? (63 - step) : step;
    int tid = threadIdx.x, ty = tid >> 6, tx = tid & 63;
    const float* hp = d_h[ping] + (size_t)dir*BATCH*HID;
    const float* wt = d_whh_t + (size_t)dir*HID*G3;
    u64 acc[8][3] = {};
    int fm = tid >> 3, fk4 = (tid & 7)*4;     // A-fill coords
    for (int kc = 0; kc < 4; kc++) {
        __syncthreads();
        {   // A fill: 32m x 32k
            float4 v = *(const float4*)&hp[(size_t)(b0+fm)*HID + kc*32 + fk4];
            As[fk4+0][fm]=v.x; As[fk4+1][fm]=v.y; As[fk4+2][fm]=v.z; As[fk4+3][fm]=v.w;
        }
        // B fill: 32k x 384, coalesced float4
#pragma unroll
        for (int p = 0; p < 12; p++) {
            int i = p*256 + tid;          // 0..3071 float4 units
            int k = i / 96, n4 = (i - k*96)*4;
            *(float4*)&Bs[k][n4] =
                *(const float4*)&wt[(size_t)(kc*32+k)*G3 + n4];
        }
        __syncthreads();
#pragma unroll 4
        for (int k = 0; k < 32; k++) {
            float4 a0 = *(const float4*)&As[k][ty*8];
            float4 a1 = *(const float4*)&As[k][ty*8+4];
            u64 br = *(const u64*)&Bs[k][tx*2];
            u64 bz = *(const u64*)&Bs[k][128 + tx*2];
            u64 bn = *(const u64*)&Bs[k][256 + tx*2];
            float av[8] = {a0.x,a0.y,a0.z,a0.w,a1.x,a1.y,a1.z,a1.w};
#pragma unroll
            for (int i = 0; i < 8; i++) {
                u64 aa; PK2(aa, av[i]);
                FMA2(acc[i][0], aa, br);
                FMA2(acc[i][1], aa, bz);
                FMA2(acc[i][2], aa, bn);
            }
        }
    }
    // cell epilogue — everything in registers
    int j0 = tx*2;
    const float* bh = bhh + dir*G3;
    float2 bhr = *(const float2*)&bh[j0];
    float2 bhz = *(const float2*)&bh[128 + j0];
    float2 bhn = *(const float2*)&bh[256 + j0];
    size_t xzb = ((size_t)(dir*64 + sx)*BATCH + b0)*G3;
    float* hout = d_h[1-ping] + (size_t)dir*BATCH*HID;
#pragma unroll
    for (int i = 0; i < 8; i++) {
        int m = ty*8 + i, b = b0 + m;
        const float* xgp = &d_xg[xzb + (size_t)m*G3];
        float2 xr = *(const float2*)&xgp[j0];
        float2 xz = *(const float2*)&xgp[128 + j0];
        float2 xn = *(const float2*)&xgp[256 + j0];
        float2 hpv = *(const float2*)&hp[(size_t)b*HID + j0];
        float hr0,hr1,hz0,hz1,hn0,hn1;
        UPK2(hr0,hr1,acc[i][0]); UPK2(hz0,hz1,acc[i][1]); UPK2(hn0,hn1,acc[i][2]);
        float r0 = 1.f/(1.f + expf(-(xr.x + hr0 + bhr.x)));
        float r1 = 1.f/(1.f + expf(-(xr.y + hr1 + bhr.y)));
        float z0 = 1.f/(1.f + expf(-(xz.x + hz0 + bhz.x)));
        float z1 = 1.f/(1.f + expf(-(xz.y + hz1 + bhz.y)));
        float n0 = tanhf(xn.x + r0*(hn0 + bhn.x));
        float n1 = tanhf(xn.y + r1*(hn1 + bhn.y));
        float h0 = (1.f - z0)*n0 + z0*hpv.x;
        float h1 = (1.f - z1)*n1 + z1*hpv.y;
        *(float2*)&hout[(size_t)b*HID + j0] = make_float2(h0, h1);
        *(float2*)&d_go[((size_t)b*64 + sx)*256 + dir*128 + j0] = make_float2(h0, h1);
    }
}

// ---------------- w_x = go @ Wx^T: 256x64 tile, f32x2 -------------------------
__global__ __launch_bounds__(256,2) void k_wx() {
    __shared__ __align__(16) float As[32][260];
    __shared__ __align__(16) float Bs[32][68];
    int m0 = blockIdx.x*256;
    int tid = threadIdx.x, ty = tid >> 3, tx = tid & 7;
    u64 acc[8][4] = {};
    for (int kc = 0; kc < 8; kc++) {
        __syncthreads();
#pragma unroll
        for (int p = 0; p < 8; p++) {
            int i = p*256 + tid;
            int m = i >> 3, k4 = (i & 7)*4;
            float4 v = *(const float4*)&d_go[(size_t)(m0+m)*256 + kc*32 + k4];
            As[k4+0][m]=v.x; As[k4+1][m]=v.y; As[k4+2][m]=v.z; As[k4+3][m]=v.w;
        }
        for (int i = tid; i < 32*16; i += 256) {
            int k = i >> 4, n4 = (i & 15)*4;
            *(float4*)&Bs[k][n4] = *(const float4*)&d_wxt[(size_t)(kc*32+k)*64 + n4];
        }
        __syncthreads();
#pragma unroll 4
        for (int k = 0; k < 32; k++) {
            float4 a0 = *(const float4*)&As[k][ty*8];
            float4 a1 = *(const float4*)&As[k][ty*8+4];
            ulonglong2 b0 = *(const ulonglong2*)&Bs[k][tx*8];
            ulonglong2 b1 = *(const ulonglong2*)&Bs[k][tx*8+4];
            ROW8(acc[0], a0.x) ROW8(acc[1], a0.y) ROW8(acc[2], a0.z) ROW8(acc[3], a0.w)
            ROW8(acc[4], a1.x) ROW8(acc[5], a1.y) ROW8(acc[6], a1.z) ROW8(acc[7], a1.w)
        }
    }
#pragma unroll
    for (int i=0;i<8;i++) {
        int m = m0 + ty*8 + i;
        float o[8];
#pragma unroll
        for (int j=0;j<4;j++) UPK2(o[2*j], o[2*j+1], acc[i][j]);
        *(float4*)&d_wx[(size_t)m*64 + tx*8]     = make_float4(o[0],o[1],o[2],o[3]);
        *(float4*)&d_wx[(size_t)m*64 + tx*8 + 4] = make_float4(o[4],o[5],o[6],o[7]);
    }
}

// ---------------- gx[b,c] = sum_s go[b,s,c] * xhat[b,s] -----------------------
__global__ __launch_bounds__(256) void k_gx(const float* __restrict__ x_raw) {
    int b = blockIdx.x;
    int c = threadIdx.x;
    __shared__ float xh[64];
    if (c < 64) xh[c] = 2.f*x_raw[b*64+c] - 3.f;
    __syncthreads();
    float acc = 0.f;
    const float* g = d_go + (size_t)b*64*256;
#pragma unroll 8
    for (int s=0;s<64;s++) acc += g[s*256+c]*xh[s];
    d_gx[(size_t)b*256 + c] = acc;
}

// ---------------- final per-batch: z0, GD loop, output ------------------------
__global__ __launch_bounds__(256) void k_final(const float* __restrict__ Wz,
                                               float* __restrict__ outp) {
    int b = blockIdx.x, tid = threadIdx.x;
    __shared__ float Ws[64][65];
    __shared__ float As[64][65];
    __shared__ float hy[64], zv[64], wh[64], t1[64], t2[64];
    __shared__ float gxs[256];
    for (int i=tid;i<4096;i+=256) Ws[i>>6][i&63] = d_wx[(size_t)b*4096 + i];
    for (int i=tid;i<4096;i+=256) As[i>>6][i&63] = d_HtH[(size_t)b*4096 + i];
    if (tid<64) hy[tid] = d_Hty[b*64+tid];
    gxs[tid] = d_gx[(size_t)b*256 + tid];
    __syncthreads();
    if (tid<64) {
        float a=0.f;
        const float* wz = Wz + tid*256;
#pragma unroll 8
        for (int c=0;c<256;c++) a += wz[c]*gxs[c];
        zv[tid] = a;
        float w=0.f;
#pragma unroll
        for (int s=0;s<64;s++) w += Ws[s][tid]*hy[s];
        wh[tid] = w;
    }
    __syncthreads();
    for (int it=0; it<10; it++) {
        if (tid<64) { float a=0.f;
#pragma unroll
            for (int zc=0;zc<64;zc++) a += Ws[tid][zc]*zv[zc];
            t1[tid]=a; }
        __syncthreads();
        if (tid<64) { float a=0.f;
#pragma unroll
            for (int u=0;u<64;u++) a += As[tid][u]*t1[u];
            t2[tid]=a; }
        __syncthreads();
        if (tid<64) { float a=0.f;
#pragma unroll
            for (int s=0;s<64;s++) a += Ws[s][tid]*t2[s];
            zv[tid] += 2e-6f*(wh[tid]-a); }
        __syncthreads();
    }
    if (tid<64) {
        float a=0.f;
#pragma unroll
        for (int zc=0;zc<64;zc++) a += Ws[tid][zc]*zv[zc];
        outp[b*64+tid] = a;
    }
}

// ---------------- launch -------------------------------------------------------
extern "C" void kernel_launch(void* const* d_in, const int* in_sizes, int n_in,
                              void* d_out, int out_size) {
    const float* y     = (const float*)d_in[0];
    const float* H     = (const float*)d_in[1];
    const float* xraw  = (const float*)d_in[2];
    const float* wih   = (const float*)d_in[3];
    const float* whh   = (const float*)d_in[4];
    const float* bih   = (const float*)d_in[5];
    const float* bhh   = (const float*)d_in[6];
    const float* Wz    = (const float*)d_in[7];
    const float* Wx    = (const float*)d_in[8];
    const float* gamma = (const float*)d_in[9];
    const float* beta  = (const float*)d_in[10];
    float* outp = (float*)d_out;

    cudaFuncSetAttribute(k_xg, cudaFuncAttributeMaxDynamicSharedMemorySize, XG_SMEM);

    k_init<<<8192,256>>>();
    k_prep<<<384,256>>>(wih, whh, Wx);
    k_hth<<<BATCH,256>>>(H, y);
    k_bn<<<1,768>>>(gamma, beta, wih);
    k_xg<<<dim3(3,64,128),256,XG_SMEM>>>(bih);
    for (int step=0; step<64; step++) {
        k_gru_step<<<dim3(256,2),256>>>(bhh, step, step & 1);
    }
    k_wx<<<2048,256>>>();
    k_gx<<<BATCH,256>>>(xraw);
    k_final<<<BATCH,256>>>(Wz, outp);
}